// round 6
// baseline (speedup 1.0000x reference)
#include <cuda_runtime.h>
#include <cuda_bf16.h>
#include <cstdint>

// ---------------- accurate activations (ex2 ~2^-22, rcp ~1ulp) ----------------
static __device__ __forceinline__ float ex2f(float x){
    float r; asm("ex2.approx.f32 %0, %1;" : "=f"(r) : "f"(x)); return r;
}
static __device__ __forceinline__ float rcpf(float x){
    float r; asm("rcp.approx.f32 %0, %1;" : "=f"(r) : "f"(x)); return r;
}
#define L2E 1.4426950408889634f
static __device__ __forceinline__ float sigmoid_acc(float x){
    return rcpf(1.0f + ex2f(-x * L2E));
}
static __device__ __forceinline__ float tanh_acc(float x){
    return 1.0f - 2.0f * rcpf(ex2f(2.0f * L2E * x) + 1.0f);
}

#define TT 8192
#define HH 128
#define II 16
#define PP 1024
#define GG 512   // 4*H

// W_hh transposed for coalesced streaming:
// layout [j>>2][g][j&3]  (flat index ((jc*512 + g)<<2) + (j&3)).
// A warp loading float4 at (jc, g=lane base) touches 512 contiguous bytes.
__device__ float g_WhhT[32 * 512 * 4];

__global__ void __launch_bounds__(256) transpose_whh_kernel(const float* __restrict__ Whh){
    int idx = blockIdx.x * 256 + threadIdx.x;      // 65536 total
    int g = idx >> 7;
    int j = idx & 127;
    g_WhhT[(((j >> 2) * 512 + g) << 2) + (j & 3)] = Whh[idx];
}

// Simple, machinery-free LSTM: one CTA per batch element, 512 threads,
// thread g owns gate row g. h/c/gates via SMEM + __syncthreads only.
__global__ void __launch_bounds__(512, 1)
lstm_simple_kernel(const float* __restrict__ x,
                   const float* __restrict__ Wih,
                   const float* __restrict__ bih,
                   const float* __restrict__ bhh,
                   const float* __restrict__ Wfc,
                   const float* __restrict__ bfc,
                   float* __restrict__ out)
{
    __shared__ float xsh[2][II];        // double-buffered x row
    __shared__ float hsh[HH];           // hidden state
    __shared__ float act[GG];           // activated gates
    __shared__ float sums_s[PP * 3];
    __shared__ float cnt_s[PP];

    const int tid = threadIdx.x;
    const int wid = tid >> 5;
    const int lid = tid & 31;
    const int b   = blockIdx.x;

    // per-thread W_ih row (16 regs) + fused bias
    float wih_r[II];
    #pragma unroll
    for (int i = 0; i < II; i++) wih_r[i] = Wih[tid * II + i];
    const float bias = bih[tid] + bhh[tid];

    // FC head: warp ch (0..2) owns output channel ch
    float wf0 = 0.f, wf1 = 0.f, wf2 = 0.f, wf3 = 0.f, bo = 0.f;
    if (wid < 3){
        wf0 = Wfc[wid * HH + lid];      wf1 = Wfc[wid * HH + 32 + lid];
        wf2 = Wfc[wid * HH + 64 + lid]; wf3 = Wfc[wid * HH + 96 + lid];
        bo  = bfc[wid];
    }

    if (tid < HH) hsh[tid] = 0.f;
    for (int k = tid; k < PP; k += 512)     cnt_s[k]  = 0.f;
    for (int k = tid; k < 3 * PP; k += 512) sums_s[k] = 0.f;

    float c = 0.f;                       // cell state, threads 0..127
    const float* xb = x + (size_t)b * TT * II;

    if (tid < II) xsh[0][tid] = xb[tid];   // x(0)
    __syncthreads();

    const bool is_tanh_gate = ((tid >> 7) == 2);   // rows 256..383 = g gate

    for (int t = 0; t < TT; t++){
        const int pb = t & 1;

        // stage 0: prefetch x(t+1) into the other buffer (consumed next step)
        if (tid < II){
            int tn = t + 1; if (tn > TT - 1) tn = TT - 1;
            xsh[pb ^ 1][tid] = __ldg(xb + (size_t)tn * II + tid);
        }

        // stage 1: gpre = W_hh[g,:]*h + W_ih[g,:]*x + bias
        float acc = bias;
        #pragma unroll
        for (int jc = 0; jc < 32; jc++){
            const float4 w4 = *reinterpret_cast<const float4*>(
                g_WhhT + (((jc * 512 + tid)) << 2));
            acc += w4.x * hsh[4*jc]   + w4.y * hsh[4*jc+1]
                 + w4.z * hsh[4*jc+2] + w4.w * hsh[4*jc+3];
        }
        #pragma unroll
        for (int i = 0; i < II; i++) acc += wih_r[i] * xsh[pb][i];

        act[tid] = is_tanh_gate ? tanh_acc(acc) : sigmoid_acc(acc);
        const float idf = xsh[pb][2];    // photo id of step t
        __syncthreads();

        // stage 2: cell/hidden update (threads 0..127)
        if (tid < HH){
            const float iv = act[tid];
            const float fv = act[HH + tid];
            const float gv = act[2*HH + tid];
            const float ov = act[3*HH + tid];
            c = fv * c + iv * gv;
            hsh[tid] = ov * tanh_acc(c);
        }
        __syncthreads();

        // stage 3: FC head + segment accumulate (warps 0..2 = channels 0..2)
        if (wid < 3){
            float v = hsh[lid]      * wf0 + hsh[32 + lid] * wf1
                    + hsh[64 + lid] * wf2 + hsh[96 + lid] * wf3;
            v += __shfl_xor_sync(0xffffffffu, v, 16);
            v += __shfl_xor_sync(0xffffffffu, v, 8);
            v += __shfl_xor_sync(0xffffffffu, v, 4);
            v += __shfl_xor_sync(0xffffffffu, v, 2);
            v += __shfl_xor_sync(0xffffffffu, v, 1);
            if (lid == 0){
                const int id = (int)idf;
                if ((unsigned)id < (unsigned)PP){
                    sums_s[id * 3 + wid] += v + bo;
                    if (wid == 0) cnt_s[id] += 1.f;
                }
            }
        }
        __syncthreads();   // protects hsh (next write) and xsh buffers
    }

    // epilogue: mean per (batch, photo)
    for (int k = tid; k < 3 * PP; k += 512){
        float cn = cnt_s[k / 3];
        if (cn == 0.f) cn = 1.f;
        out[(size_t)b * 3 * PP + k] = sums_s[k] / cn;
    }
}

extern "C" void kernel_launch(void* const* d_in, const int* in_sizes, int n_in,
                              void* d_out, int out_size)
{
    // Self-heal input binding by element counts (sizes are distinct except
    // the two 512-element biases, whose order is irrelevant: only the sum
    // b_ih + b_hh is ever used).
    const float *x = 0, *Wih = 0, *Whh = 0, *b1 = 0, *b2 = 0, *Wfc = 0, *bfc = 0;
    for (int i = 0; i < n_in; i++){
        const float* p = (const float*)d_in[i];
        switch (in_sizes[i]){
            case 32*8192*16: x   = p; break;
            case 512*16:     Wih = p; break;
            case 512*128:    Whh = p; break;
            case 512:        if (!b1) b1 = p; else b2 = p; break;
            case 3*128:      Wfc = p; break;
            case 3:          bfc = p; break;
            default: break;  // num_photos scalar etc. — ignored
        }
    }
    // Fallback to canonical metadata order if size-matching failed.
    if (!x)   x   = (const float*)d_in[0];
    if (!Wih) Wih = (const float*)d_in[1];
    if (!Whh) Whh = (const float*)d_in[2];
    if (!b1)  b1  = (const float*)d_in[3];
    if (!b2)  b2  = (const float*)d_in[4];
    if (!Wfc) Wfc = (const float*)d_in[5];
    if (!bfc) bfc = (const float*)d_in[6];

    float* out = (float*)d_out;

    transpose_whh_kernel<<<256, 256>>>(Whh);
    lstm_simple_kernel<<<32, 512>>>(x, Wih, b1, b2, Wfc, bfc, out);
}

// round 7
// speedup vs baseline: 3.8500x; 3.8500x over previous
#include <cuda_runtime.h>
#include <cuda_fp16.h>
#include <cstdint>

// ---------------- accurate activations (ex2 ~2^-22, rcp ~1ulp) ----------------
static __device__ __forceinline__ float ex2f(float x){
    float r; asm("ex2.approx.f32 %0, %1;" : "=f"(r) : "f"(x)); return r;
}
static __device__ __forceinline__ float rcpf(float x){
    float r; asm("rcp.approx.f32 %0, %1;" : "=f"(r) : "f"(x)); return r;
}
#define L2E 1.4426950408889634f
static __device__ __forceinline__ float sigmoid_acc(float x){
    return rcpf(1.0f + ex2f(-x * L2E));
}
static __device__ __forceinline__ float tanh_acc(float x){
    return 1.0f - 2.0f * rcpf(ex2f(2.0f * L2E * x) + 1.0f);
}

#define TT 8192
#define HH 128
#define II 16
#define PP 1024
#define KK_TOT 144   // 128 (h) + 16 (x)
#define NKK 9        // 144 / 16

// m16n8k16 fp16 MMA, fp32 accumulate (fallback HMMA path on sm_103a).
static __device__ __forceinline__ void mma16816(
    float& d0, float& d1, float& d2, float& d3,
    uint32_t a0, uint32_t a1, uint32_t a2, uint32_t a3,
    uint32_t b0, uint32_t b1)
{
    asm("mma.sync.aligned.m16n8k16.row.col.f32.f16.f16.f32 "
        "{%0,%1,%2,%3}, {%4,%5,%6,%7}, {%8,%9}, {%0,%1,%2,%3};"
        : "+f"(d0), "+f"(d1), "+f"(d2), "+f"(d3)
        : "r"(a0), "r"(a1), "r"(a2), "r"(a3), "r"(b0), "r"(b1));
}

// W'(r,k): k<128 -> Whh[r][k], else Wih[r][k-128]. Loads adjacent (k,k+1) pair,
// packs to half2-in-u32 (low half = lower k).
static __device__ __forceinline__ uint32_t pack_w(
    const float* __restrict__ Whh, const float* __restrict__ Wih, int r, int k)
{
    float2 f;
    if (k < HH) f = *reinterpret_cast<const float2*>(Whh + (size_t)r * HH + k);
    else        f = *reinterpret_cast<const float2*>(Wih + (size_t)r * II + (k - HH));
    __half2 h = __floats2half2_rn(f.x, f.y);
    return *reinterpret_cast<uint32_t*>(&h);
}

// vB32 layout (72 u32): for k-iter kk, lane tq loads uint2 at vB32[(4kk+tq)*2]:
//   .x = {v[16kk+2tq],   v[16kk+2tq+1]}   (b0)
//   .y = {v[16kk+2tq+8], v[16kk+2tq+9]}   (b1)
// where v = [h(0..127); x(0..15)] fp16. Writer for pair j (v[2j],v[2j+1]):
//   kk=j>>3, rem=j&7 -> idx = rem<4 ? (4kk+rem)*2 : (4kk+rem-4)*2+1.
static __device__ __forceinline__ int vb_idx(int j){
    int kk = j >> 3, rem = j & 7;
    return (rem < 4) ? ((4*kk + rem)*2) : ((4*kk + rem - 4)*2 + 1);
}

// One CTA per batch element, 512 threads. Warp w owns gate rows 32w..32w+31
// (gate type = w>>2, PyTorch order i,f,g,o). W' = [W_hh | W_ih] lives in
// registers as fp16 mma A-fragments (72 u32/thread) for all 8192 steps.
__global__ void __launch_bounds__(512, 1)
lstm_mma_kernel(const float* __restrict__ x,
                const float* __restrict__ Wih,
                const float* __restrict__ Whh,
                const float* __restrict__ bih,
                const float* __restrict__ bhh,
                const float* __restrict__ Wfc,
                const float* __restrict__ bfc,
                float* __restrict__ out)
{
    __shared__ float xsh[2][II];                       // fp32 x double buffer
    __shared__ float hsh[HH];                          // fp32 h (for FC head)
    __shared__ float act[512];                         // activated gates
    __shared__ __align__(16) uint32_t vB32[72];        // [h;x] fp16 B-operand
    __shared__ float sums_s[PP * 3];
    __shared__ float cnt_s[PP];

    const int tid = threadIdx.x;
    const int wid = tid >> 5;
    const int lid = tid & 31;
    const int b   = blockIdx.x;
    const int g   = lid >> 2;    // mma row group
    const int tq  = lid & 3;     // mma thread-in-quad

    // ---- build resident A fragments: aw[tile][kk][reg] ----
    uint32_t aw[2][NKK][4];
    #pragma unroll
    for (int ti = 0; ti < 2; ti++){
        const int r0 = 32*wid + 16*ti + g;
        #pragma unroll
        for (int kk = 0; kk < NKK; kk++){
            const int k0 = 16*kk + 2*tq;
            aw[ti][kk][0] = pack_w(Whh, Wih, r0,     k0);
            aw[ti][kk][1] = pack_w(Whh, Wih, r0 + 8, k0);
            aw[ti][kk][2] = pack_w(Whh, Wih, r0,     k0 + 8);
            aw[ti][kk][3] = pack_w(Whh, Wih, r0 + 8, k0 + 8);
        }
    }
    const float bias = bih[tid] + bhh[tid];
    const bool  is_tanh_gate = ((tid >> 7) == 2);

    // FC head: warp ch (0..2) owns output channel ch
    float wf0 = 0.f, wf1 = 0.f, wf2 = 0.f, wf3 = 0.f, bo = 0.f;
    if (wid < 3){
        wf0 = Wfc[wid*HH + lid];      wf1 = Wfc[wid*HH + 32 + lid];
        wf2 = Wfc[wid*HH + 64 + lid]; wf3 = Wfc[wid*HH + 96 + lid];
        bo  = bfc[wid];
    }

    // ---- init shared state ----
    const float* xb = x + (size_t)b * TT * II;
    if (tid < HH) hsh[tid] = 0.f;
    if (tid < 64) vB32[tid] = 0u;                      // h-part of vB = 0
    if (tid >= 64 && tid < 72){                        // x-part of vB = fp16(x(0))
        int jj = tid - 64;
        __half2 xp = __floats2half2_rn(xb[2*jj], xb[2*jj + 1]);
        vB32[(jj < 4) ? (32 + jj)*2 : (32 + jj - 4)*2 + 1]
            = *reinterpret_cast<uint32_t*>(&xp);
    }
    if (tid < II){ xsh[0][tid] = xb[tid]; xsh[1][tid] = xb[II + tid]; }
    for (int k = tid; k < PP; k += 512)     cnt_s[k]  = 0.f;
    for (int k = tid; k < 3*PP; k += 512)   sums_s[k] = 0.f;
    __syncthreads();

    float c = 0.f;   // cell state (threads 0..127)

    for (int t = 0; t < TT; t++){
        // ================= S1: MMA GEMV + activations =================
        const float idf = xsh[t & 1][2];               // photo id of step t
        float xr = 0.f;
        if (tid < II){                                 // prefetch x(t+2)
            int tn = t + 2; if (tn > TT - 1) tn = TT - 1;
            xr = __ldg(xb + (size_t)tn * II + tid);
        }

        float d0=0.f,d1=0.f,d2=0.f,d3=0.f,d4=0.f,d5=0.f,d6=0.f,d7=0.f;
        #pragma unroll
        for (int kk = 0; kk < NKK; kk++){
            const uint2 bb = *reinterpret_cast<const uint2*>(&vB32[(4*kk + tq)*2]);
            mma16816(d0,d1,d2,d3, aw[0][kk][0],aw[0][kk][1],aw[0][kk][2],aw[0][kk][3], bb.x, bb.y);
            mma16816(d4,d5,d6,d7, aw[1][kk][0],aw[1][kk][1],aw[1][kk][2],aw[1][kk][3], bb.x, bb.y);
        }
        // distribute col-0 results: row (32w+l) ends up in lane l
        const int sl = (lid & 7) * 4;                  // source lane (tq==0)
        const float v0 = __shfl_sync(0xffffffffu, d0, sl);   // rows 0..7   (tile0 c0)
        const float v1 = __shfl_sync(0xffffffffu, d2, sl);   // rows 8..15  (tile0 c2)
        const float v2 = __shfl_sync(0xffffffffu, d4, sl);   // rows 16..23 (tile1 c0)
        const float v3 = __shfl_sync(0xffffffffu, d6, sl);   // rows 24..31 (tile1 c2)
        const int sel = lid >> 3;
        float gpre = (sel == 0) ? v0 : (sel == 1) ? v1 : (sel == 2) ? v2 : v3;
        gpre += bias;
        act[tid] = is_tanh_gate ? tanh_acc(gpre) : sigmoid_acc(gpre);
        __syncthreads();   // A

        // ============ S2: cell/hidden update + fp16 B refresh ============
        if (tid < HH){
            const float iv = act[tid];
            const float fv = act[HH + tid];
            const float gv = act[2*HH + tid];
            const float ov = act[3*HH + tid];
            c = fv * c + iv * gv;
            const float hn = ov * tanh_acc(c);
            hsh[tid] = hn;
            const float hn1 = __shfl_down_sync(0xffffffffu, hn, 1);
            if (!(tid & 1)){
                __half2 hp = __floats2half2_rn(hn, hn1);
                vB32[vb_idx(tid >> 1)] = *reinterpret_cast<uint32_t*>(&hp);
            }
        } else if (tid < 136){                         // x(t+1) -> fp16 B x-part
            const int jj = tid - 128;
            const float* xsrc = xsh[(t + 1) & 1];
            __half2 xp = __floats2half2_rn(xsrc[2*jj], xsrc[2*jj + 1]);
            vB32[(jj < 4) ? (32 + jj)*2 : (32 + jj - 4)*2 + 1]
                = *reinterpret_cast<uint32_t*>(&xp);
        }
        __syncthreads();   // B

        // ============ S3: FC head + segment accumulate + x store ============
        if (wid < 3){
            float v = hsh[lid]      * wf0 + hsh[32 + lid] * wf1
                    + hsh[64 + lid] * wf2 + hsh[96 + lid] * wf3;
            v += __shfl_xor_sync(0xffffffffu, v, 16);
            v += __shfl_xor_sync(0xffffffffu, v, 8);
            v += __shfl_xor_sync(0xffffffffu, v, 4);
            v += __shfl_xor_sync(0xffffffffu, v, 2);
            v += __shfl_xor_sync(0xffffffffu, v, 1);
            if (lid == 0){
                const int id = (int)idf;
                if ((unsigned)id < (unsigned)PP){
                    sums_s[id*3 + wid] += v + bo;
                    if (wid == 0) cnt_s[id] += 1.f;
                }
            }
        }
        if (tid < II) xsh[t & 1][tid] = xr;            // x(t+2) into retired buffer
    }

    // ---- epilogue: mean per (batch, photo) ----
    __syncthreads();
    for (int k = tid; k < 3*PP; k += 512){
        float cn = cnt_s[k / 3];
        if (cn == 0.f) cn = 1.f;
        out[(size_t)b * 3 * PP + k] = sums_s[k] / cn;
    }
}

extern "C" void kernel_launch(void* const* d_in, const int* in_sizes, int n_in,
                              void* d_out, int out_size)
{
    // Bind inputs by element count (distinct except the two 512-biases,
    // whose order is irrelevant: only the sum is used).
    const float *x = 0, *Wih = 0, *Whh = 0, *b1 = 0, *b2 = 0, *Wfc = 0, *bfc = 0;
    for (int i = 0; i < n_in; i++){
        const float* p = (const float*)d_in[i];
        switch (in_sizes[i]){
            case 32*8192*16: x   = p; break;
            case 512*16:     Wih = p; break;
            case 512*128:    Whh = p; break;
            case 512:        if (!b1) b1 = p; else b2 = p; break;
            case 3*128:      Wfc = p; break;
            case 3:          bfc = p; break;
            default: break;
        }
    }
    if (!x)   x   = (const float*)d_in[0];
    if (!Wih) Wih = (const float*)d_in[1];
    if (!Whh) Whh = (const float*)d_in[2];
    if (!b1)  b1  = (const float*)d_in[3];
    if (!b2)  b2  = (const float*)d_in[4];
    if (!Wfc) Wfc = (const float*)d_in[5];
    if (!bfc) bfc = (const float*)d_in[6];

    float* out = (float*)d_out;
    lstm_mma_kernel<<<32, 512>>>(x, Wih, Whh, b1, b2, Wfc, bfc, out);
}